// round 1
// baseline (speedup 1.0000x reference)
#include <cuda_runtime.h>
#include <math.h>

// Problem constants (fixed by the dataset)
#define BB 8
#define HH 64
#define WW 64
#define CC 256
#define FF 256
#define NPIX (BB*HH*WW)   // 32768

// Scratch for offset/mask branch output: per pixel 27 values
// [0..17] = offsets (dy,dx per kernel point), [18..26] = mask (2*sigmoid)
__device__ float g_om[NPIX * 27];

// ---------------------------------------------------------------------------
// Kernel 1: offset/mask conv. GEMM M=32768 (pixels), K=2304, N=27 (pad to 32).
// Block = 32 pixels (half row), 256 threads = 32 px * 8 fgroups (f4).
// Per tap: stage w slice [256][32] in smem (f padded, pad cols = 0),
// read x patch rows straight from gmem (L1-resident across taps/fg-broadcast).
// ---------------------------------------------------------------------------
__global__ __launch_bounds__(256) void om_conv_kernel(
    const float* __restrict__ x,     // [B,H,W,C]
    const float* __restrict__ omw,   // [3,3,C,27]
    const float* __restrict__ omb)   // [27]
{
    __shared__ float ws[256 * 32];

    const int bid = blockIdx.x;       // 1024 blocks
    const int xh  = bid & 1;
    const int y   = (bid >> 1) & 63;
    const int b   = bid >> 7;
    const int x0  = xh * 32;
    const int tid = threadIdx.x;
    const int p   = tid >> 3;         // pixel 0..31
    const int fg  = tid & 7;          // feature group (4 f each)

    // zero-init ws (pad columns f=27..31 stay zero for all taps)
    for (int i = tid; i < 256 * 32; i += 256) ws[i] = 0.f;

    float4 acc = make_float4(0.f, 0.f, 0.f, 0.f);
    const int gx = x0 + p;

    for (int tap = 0; tap < 9; ++tap) {
        __syncthreads();
        // load w slice for this tap: ws[c*32 + f]
        for (int i = tid; i < 256 * 27; i += 256) {
            int c = i / 27;
            int f = i - c * 27;
            ws[c * 32 + f] = omw[(tap * 256 + c) * 27 + f];
        }
        __syncthreads();

        const int dy = tap / 3;
        const int dx = tap - dy * 3;
        const int sy = y - 1 + dy;
        const int sx = gx - 1 + dx;
        if ((unsigned)sy < 64u && (unsigned)sx < 64u) {
            const float* xr = x + (((b * 64 + sy) * 64) + sx) * 256;
            #pragma unroll 4
            for (int c4 = 0; c4 < 64; ++c4) {
                float4 xv = *(const float4*)(xr + c4 * 4);
                const float* wp = &ws[(c4 * 4) * 32 + fg * 4];
                float4 w0 = *(const float4*)(wp);
                float4 w1 = *(const float4*)(wp + 32);
                float4 w2 = *(const float4*)(wp + 64);
                float4 w3 = *(const float4*)(wp + 96);
                acc.x = fmaf(xv.x, w0.x, acc.x);
                acc.y = fmaf(xv.x, w0.y, acc.y);
                acc.z = fmaf(xv.x, w0.z, acc.z);
                acc.w = fmaf(xv.x, w0.w, acc.w);
                acc.x = fmaf(xv.y, w1.x, acc.x);
                acc.y = fmaf(xv.y, w1.y, acc.y);
                acc.z = fmaf(xv.y, w1.z, acc.z);
                acc.w = fmaf(xv.y, w1.w, acc.w);
                acc.x = fmaf(xv.z, w2.x, acc.x);
                acc.y = fmaf(xv.z, w2.y, acc.y);
                acc.z = fmaf(xv.z, w2.z, acc.z);
                acc.w = fmaf(xv.z, w2.w, acc.w);
                acc.x = fmaf(xv.w, w3.x, acc.x);
                acc.y = fmaf(xv.w, w3.y, acc.y);
                acc.z = fmaf(xv.w, w3.z, acc.z);
                acc.w = fmaf(xv.w, w3.w, acc.w);
            }
        }
    }

    // epilogue: add bias; transform mask channels (f>=18) to 2*sigmoid
    const int pix = (b * 64 + y) * 64 + gx;
    float vals[4] = {acc.x, acc.y, acc.z, acc.w};
    #pragma unroll
    for (int ff = 0; ff < 4; ++ff) {
        int f = fg * 4 + ff;
        if (f < 27) {
            float v = vals[ff] + omb[f];
            if (f >= 18) v = 2.f / (1.f + expf(-v));
            g_om[pix * 27 + f] = v;
        }
    }
}

// ---------------------------------------------------------------------------
// Kernel 2: fused deformable sampling + main GEMM.
// Block = 32 pixels (half row), 256 threads. Loop over 9 kernel points:
//   phase 1: sample modulated bilinear cols into smem [32][260]
//   phase 2: GEMM chunk K=256: thread owns 8 px x 4 f (acc[8][4])
// ---------------------------------------------------------------------------
__global__ __launch_bounds__(256) void dcn_main_kernel(
    const float* __restrict__ x,     // [B,H,W,C]
    const float* __restrict__ W,     // [2304,256]
    const float* __restrict__ bias,  // [256]
    float* __restrict__ out)         // [B,H,W,F]
{
    __shared__ float cols_s[32 * 260];

    const int bid = blockIdx.x;       // 1024 blocks
    const int xh  = bid & 1;
    const int y   = (bid >> 1) & 63;
    const int b   = bid >> 7;
    const int x0c = xh * 32;
    const int tid = threadIdx.x;
    // sampling role
    const int sp = tid >> 3;          // pixel 0..31
    const int sg = tid & 7;           // channel group
    // gemm role
    const int fg = tid >> 2;          // 0..63 (4 features each)
    const int pg = tid & 3;           // pixel phase (owns pixels pg+4*pp)

    const int pixbase = (b * 64 + y) * 64 + x0c;

    float acc[8][4];
    #pragma unroll
    for (int pp = 0; pp < 8; ++pp)
        #pragma unroll
        for (int ff = 0; ff < 4; ++ff) acc[pp][ff] = 0.f;

    const float* omp = g_om + (pixbase + sp) * 27;
    const float* xb  = x + b * (64 * 64 * 256);

    for (int kp = 0; kp < 9; ++kp) {
        __syncthreads();   // protect cols_s against previous GEMM reads
        {
            const int ky = kp / 3;
            const int kx = kp - ky * 3;
            float dyo = omp[2 * kp];
            float dxo = omp[2 * kp + 1];
            float m   = omp[18 + kp];
            float py = (float)(y - 1 + ky) + dyo;
            float px = (float)(x0c + sp - 1 + kx) + dxo;
            float y0f = floorf(py), x0f = floorf(px);
            float wy1 = py - y0f, wy0 = 1.f - wy1;
            float wx1 = px - x0f, wx0 = 1.f - wx1;
            int iy0 = (int)y0f, ix0 = (int)x0f;
            int iy1 = iy0 + 1,  ix1 = ix0 + 1;
            bool vy0 = (unsigned)iy0 < 64u, vy1 = (unsigned)iy1 < 64u;
            bool vx0 = (unsigned)ix0 < 64u, vx1 = (unsigned)ix1 < 64u;
            int cy0 = min(max(iy0, 0), 63), cy1 = min(max(iy1, 0), 63);
            int cx0 = min(max(ix0, 0), 63), cx1 = min(max(ix1, 0), 63);
            float w00 = (vy0 && vx0) ? wy0 * wx0 * m : 0.f;
            float w01 = (vy0 && vx1) ? wy0 * wx1 * m : 0.f;
            float w10 = (vy1 && vx0) ? wy1 * wx0 * m : 0.f;
            float w11 = (vy1 && vx1) ? wy1 * wx1 * m : 0.f;
            const float* p00 = xb + (cy0 * 64 + cx0) * 256;
            const float* p01 = xb + (cy0 * 64 + cx1) * 256;
            const float* p10 = xb + (cy1 * 64 + cx0) * 256;
            const float* p11 = xb + (cy1 * 64 + cx1) * 256;
            float* cd = &cols_s[sp * 260];
            #pragma unroll
            for (int i = 0; i < 8; ++i) {
                int c = sg * 4 + i * 32;
                float4 v00 = *(const float4*)(p00 + c);
                float4 v01 = *(const float4*)(p01 + c);
                float4 v10 = *(const float4*)(p10 + c);
                float4 v11 = *(const float4*)(p11 + c);
                float4 r;
                r.x = w00 * v00.x + w01 * v01.x + w10 * v10.x + w11 * v11.x;
                r.y = w00 * v00.y + w01 * v01.y + w10 * v10.y + w11 * v11.y;
                r.z = w00 * v00.z + w01 * v01.z + w10 * v10.z + w11 * v11.z;
                r.w = w00 * v00.w + w01 * v01.w + w10 * v10.w + w11 * v11.w;
                *(float4*)(cd + c) = r;
            }
        }
        __syncthreads();

        // GEMM: K-chunk of 256 for this kernel point
        const float* Wk = W + kp * 256 * 256 + fg * 4;
        #pragma unroll 2
        for (int k4 = 0; k4 < 64; ++k4) {
            float4 cw[8];
            #pragma unroll
            for (int pp = 0; pp < 8; ++pp)
                cw[pp] = *(const float4*)&cols_s[(pg + 4 * pp) * 260 + k4 * 4];
            #pragma unroll
            for (int kk = 0; kk < 4; ++kk) {
                float4 wv = *(const float4*)&Wk[(k4 * 4 + kk) * 256];
                #pragma unroll
                for (int pp = 0; pp < 8; ++pp) {
                    float cv = (kk == 0) ? cw[pp].x :
                               (kk == 1) ? cw[pp].y :
                               (kk == 2) ? cw[pp].z : cw[pp].w;
                    acc[pp][0] = fmaf(cv, wv.x, acc[pp][0]);
                    acc[pp][1] = fmaf(cv, wv.y, acc[pp][1]);
                    acc[pp][2] = fmaf(cv, wv.z, acc[pp][2]);
                    acc[pp][3] = fmaf(cv, wv.w, acc[pp][3]);
                }
            }
        }
    }

    // epilogue: bias add, store
    float4 bv = *(const float4*)&bias[fg * 4];
    #pragma unroll
    for (int pp = 0; pp < 8; ++pp) {
        float4 r;
        r.x = acc[pp][0] + bv.x;
        r.y = acc[pp][1] + bv.y;
        r.z = acc[pp][2] + bv.z;
        r.w = acc[pp][3] + bv.w;
        *(float4*)&out[(pixbase + pg + 4 * pp) * 256 + fg * 4] = r;
    }
}

extern "C" void kernel_launch(void* const* d_in, const int* in_sizes, int n_in,
                              void* d_out, int out_size) {
    (void)in_sizes; (void)n_in; (void)out_size;
    const float* x    = (const float*)d_in[0];   // [8,64,64,256]
    const float* omw  = (const float*)d_in[1];   // [3,3,256,27]
    const float* omb  = (const float*)d_in[2];   // [27]
    const float* W    = (const float*)d_in[3];   // [2304,256]
    const float* bias = (const float*)d_in[4];   // [256]
    float* out = (float*)d_out;

    om_conv_kernel<<<1024, 256>>>(x, omw, omb);
    dcn_main_kernel<<<1024, 256>>>(x, W, bias, out);
}

// round 3
// speedup vs baseline: 1.4852x; 1.4852x over previous
#include <cuda_runtime.h>
#include <cstdint>
#include <math.h>

// Problem constants (fixed by the dataset)
#define BB 8
#define HH 64
#define WW 64
#define CC 256
#define FF 256
#define NPIX (BB*HH*WW)   // 32768
#define KTOT 2304         // 9*256

// Scratch: offset/mask branch output (27 per pixel) and transposed tf32 weights
__device__ float g_om[NPIX * 27];
__device__ uint32_t g_Wt[FF * KTOT];   // [256][2304]  Wt[f][k] = tf32(W[k][f])

// ============================ helpers ============================
__device__ __forceinline__ uint32_t smem_u32(const void* p) {
    uint32_t a;
    asm("{ .reg .u64 t; cvta.to.shared.u64 t, %1; cvt.u32.u64 %0, t; }"
        : "=r"(a) : "l"(p));
    return a;
}
__device__ __forceinline__ uint32_t f2tf32(float f) {
    uint32_t o;
    asm("cvt.rna.tf32.f32 %0, %1;" : "=r"(o) : "f"(f));
    return o;
}
#define CP_ASYNC16(dst, src) \
    asm volatile("cp.async.cg.shared.global [%0], [%1], 16;" :: "r"(dst), "l"(src) : "memory")
#define CP_COMMIT() asm volatile("cp.async.commit_group;" ::: "memory")
#define CP_WAIT0()  asm volatile("cp.async.wait_group 0;" ::: "memory")

__device__ __forceinline__ void mma_tf32(float* c, const uint32_t* a, const uint32_t* b) {
    asm volatile("mma.sync.aligned.m16n8k8.row.col.f32.tf32.tf32.f32 "
        "{%0,%1,%2,%3}, {%4,%5,%6,%7}, {%8,%9}, {%0,%1,%2,%3};"
        : "+f"(c[0]), "+f"(c[1]), "+f"(c[2]), "+f"(c[3])
        : "r"(a[0]), "r"(a[1]), "r"(a[2]), "r"(a[3]), "r"(b[0]), "r"(b[1]));
}

// ============================ Kernel 0: W transpose + tf32 round ==============
__global__ __launch_bounds__(256) void transpose_w(const float* __restrict__ W) {
    __shared__ float t[32][33];
    int k0 = blockIdx.x * 32, f0 = blockIdx.y * 32;
    int tx = threadIdx.x & 31, ty = threadIdx.x >> 5;   // 32x8
    #pragma unroll
    for (int r = 0; r < 32; r += 8)
        t[ty + r][tx] = W[(k0 + ty + r) * 256 + f0 + tx];
    __syncthreads();
    #pragma unroll
    for (int r = 0; r < 32; r += 8)
        g_Wt[(f0 + ty + r) * KTOT + k0 + tx] = f2tf32(t[tx][ty + r]);
}

// ============================ Kernel 1: offset/mask conv (fp32) ==============
__global__ __launch_bounds__(256) void om_conv_kernel(
    const float* __restrict__ x, const float* __restrict__ omw,
    const float* __restrict__ omb)
{
    __shared__ float ws[256 * 32];
    const int bid = blockIdx.x;
    const int xh = bid & 1;
    const int y = (bid >> 1) & 63;
    const int b = bid >> 7;
    const int x0 = xh * 32;
    const int tid = threadIdx.x;
    const int p = tid >> 3;
    const int fg = tid & 7;

    for (int i = tid; i < 256 * 32; i += 256) ws[i] = 0.f;

    float4 acc = make_float4(0.f, 0.f, 0.f, 0.f);
    const int gx = x0 + p;

    for (int tap = 0; tap < 9; ++tap) {
        __syncthreads();
        for (int i = tid; i < 256 * 27; i += 256) {
            int c = i / 27;
            int f = i - c * 27;
            ws[c * 32 + f] = omw[(tap * 256 + c) * 27 + f];
        }
        __syncthreads();
        const int dy = tap / 3;
        const int dx = tap - dy * 3;
        const int sy = y - 1 + dy;
        const int sx = gx - 1 + dx;
        if ((unsigned)sy < 64u && (unsigned)sx < 64u) {
            const float* xr = x + (((b * 64 + sy) * 64) + sx) * 256;
            #pragma unroll 4
            for (int c4 = 0; c4 < 64; ++c4) {
                float4 xv = *(const float4*)(xr + c4 * 4);
                const float* wp = &ws[(c4 * 4) * 32 + fg * 4];
                float4 w0 = *(const float4*)(wp);
                float4 w1 = *(const float4*)(wp + 32);
                float4 w2 = *(const float4*)(wp + 64);
                float4 w3 = *(const float4*)(wp + 96);
                acc.x = fmaf(xv.x, w0.x, acc.x); acc.y = fmaf(xv.x, w0.y, acc.y);
                acc.z = fmaf(xv.x, w0.z, acc.z); acc.w = fmaf(xv.x, w0.w, acc.w);
                acc.x = fmaf(xv.y, w1.x, acc.x); acc.y = fmaf(xv.y, w1.y, acc.y);
                acc.z = fmaf(xv.y, w1.z, acc.z); acc.w = fmaf(xv.y, w1.w, acc.w);
                acc.x = fmaf(xv.z, w2.x, acc.x); acc.y = fmaf(xv.z, w2.y, acc.y);
                acc.z = fmaf(xv.z, w2.z, acc.z); acc.w = fmaf(xv.z, w2.w, acc.w);
                acc.x = fmaf(xv.w, w3.x, acc.x); acc.y = fmaf(xv.w, w3.y, acc.y);
                acc.z = fmaf(xv.w, w3.z, acc.z); acc.w = fmaf(xv.w, w3.w, acc.w);
            }
        }
    }
    const int pix = (b * 64 + y) * 64 + gx;
    float vals[4] = {acc.x, acc.y, acc.z, acc.w};
    #pragma unroll
    for (int ff = 0; ff < 4; ++ff) {
        int f = fg * 4 + ff;
        if (f < 27) {
            float v = vals[ff] + omb[f];
            if (f >= 18) v = 2.f / (1.f + expf(-v));
            g_om[pix * 27 + f] = v;
        }
    }
}

// ============================ Kernel 2: fused sampling + mma.sync TF32 GEMM ===
// CTA tile: M=128 pixels x N=128 features. Grid 512 = 256 m-tiles x 2 n-halves.
// 8 warps in 4(m) x 2(n); warp tile 32x64 -> 2 m16 x 8 n8 mma tiles, acc 64 f32.
// K loop: 72 chunks of 32 (9 kernel points x 8 channel segments).
//
// SMEM (dynamic, 73728 B):
//   SW [2][4][128] f32 (4KB)   bilinear weights, double-buffered per kernel pt
//   SO [2][4][128] i32 (4KB)   corner offsets
//   SA [2][128][32] f32 (32KB) A stage, row = 128B, elem (m,k) at k^((m&7)*4)
//   SB [2][16][8][32] f32 (32KB) B stage, fragment-major: [ntile][kq][slot]
//       slot(f,k) = ((f&7)^kq)*4 + (k&3),  kq = (k>>2)
#define SM2_SW 0
#define SM2_SO 4096
#define SM2_A  8192
#define SM2_B  40960
#define SM2_TOTAL 73728

__device__ __forceinline__ void compute_params2(int kp, int m, int p,
                                                float* sw, int* so) {
    const float* omp = g_om + m * 27;
    const int y = (m >> 6) & 63, xc = m & 63, b = m >> 12;
    const int ky = kp / 3, kx = kp - ky * 3;
    float py = (float)(y - 1 + ky) + omp[2 * kp];
    float px = (float)(xc - 1 + kx) + omp[2 * kp + 1];
    float msk = omp[18 + kp];
    float y0f = floorf(py), x0f = floorf(px);
    float wy1 = py - y0f, wy0 = 1.f - wy1;
    float wx1 = px - x0f, wx0 = 1.f - wx1;
    int iy0 = (int)y0f, ix0 = (int)x0f;
    int iy1 = iy0 + 1, ix1 = ix0 + 1;
    bool vy0 = (unsigned)iy0 < 64u, vy1 = (unsigned)iy1 < 64u;
    bool vx0 = (unsigned)ix0 < 64u, vx1 = (unsigned)ix1 < 64u;
    int cy0 = min(max(iy0, 0), 63), cy1 = min(max(iy1, 0), 63);
    int cx0 = min(max(ix0, 0), 63), cx1 = min(max(ix1, 0), 63);
    int base = b << 12;
    so[0 * 128 + p] = (base + cy0 * 64 + cx0) << 8;
    so[1 * 128 + p] = (base + cy0 * 64 + cx1) << 8;
    so[2 * 128 + p] = (base + cy1 * 64 + cx0) << 8;
    so[3 * 128 + p] = (base + cy1 * 64 + cx1) << 8;
    sw[0 * 128 + p] = (vy0 && vx0) ? wy0 * wx0 * msk : 0.f;
    sw[1 * 128 + p] = (vy0 && vx1) ? wy0 * wx1 * msk : 0.f;
    sw[2 * 128 + p] = (vy1 && vx0) ? wy1 * wx0 * msk : 0.f;
    sw[3 * 128 + p] = (vy1 && vx1) ? wy1 * wx1 * msk : 0.f;
}

// Sample chunk j into A stage: 256 threads, 2 per pixel, 16 channels each.
__device__ __forceinline__ void sample2(const float* __restrict__ x,
                                        char* smem, int j, int stage, int tid) {
    const int pb = ((j >> 3) & 1);
    const float* sw = (const float*)(smem + SM2_SW) + pb * 512;
    const int*   so = (const int*)(smem + SM2_SO) + pb * 512;
    uint32_t* dst = (uint32_t*)(smem + SM2_A + stage * 16384);
    const int px = tid >> 1, half = tid & 1;
    const float w00 = sw[px], w01 = sw[128 + px];
    const float w10 = sw[256 + px], w11 = sw[384 + px];
    const float* b00 = x + so[px];
    const float* b01 = x + so[128 + px];
    const float* b10 = x + so[256 + px];
    const float* b11 = x + so[384 + px];
    const int cbase = (j & 7) * 32 + half * 16;
    const int xk = (px & 7) * 4;
    uint32_t* drow = dst + px * 32;
    #pragma unroll
    for (int ii = 0; ii < 4; ++ii) {
        const int c = cbase + ii * 4;
        float4 v00 = *(const float4*)(b00 + c);
        float4 v01 = *(const float4*)(b01 + c);
        float4 v10 = *(const float4*)(b10 + c);
        float4 v11 = *(const float4*)(b11 + c);
        uint4 r;
        r.x = f2tf32(w00 * v00.x + w01 * v01.x + w10 * v10.x + w11 * v11.x);
        r.y = f2tf32(w00 * v00.y + w01 * v01.y + w10 * v10.y + w11 * v11.y);
        r.z = f2tf32(w00 * v00.z + w01 * v01.z + w10 * v10.z + w11 * v11.z);
        r.w = f2tf32(w00 * v00.w + w01 * v01.w + w10 * v10.w + w11 * v11.w);
        const int kloc = (half * 16 + ii * 4) ^ xk;
        *(uint4*)(drow + kloc) = r;
    }
}

// Stage B chunk j (32 x 128 tf32) via cp.async into fragment-major layout.
__device__ __forceinline__ void loadB2(uint32_t sb_u32, int f0, int j,
                                       int stage, int tid) {
    const uint32_t base = sb_u32 + SM2_B + stage * 16384;
    #pragma unroll
    for (int it = 0; it < 4; ++it) {
        const int g = it * 256 + tid;       // 1024 granules
        const int f = g >> 3, kq = g & 7;
        const uint32_t* src = g_Wt + (size_t)(f0 + f) * KTOT + j * 32 + kq * 4;
        const uint32_t dst = base + (((f >> 3) * 8 + kq) * 32 + ((f & 7) ^ kq) * 4) * 4;
        CP_ASYNC16(dst, src);
    }
}

__global__ __launch_bounds__(256, 2) void dcn_mma_kernel(
    const float* __restrict__ x,      // [8,64,64,256]
    const float* __restrict__ bias,   // [256]
    float* __restrict__ out)          // [32768,256]
{
    extern __shared__ char smem[];
    const uint32_t sb = smem_u32(smem);
    const int tid = threadIdx.x;
    const int l = tid & 31, wid = tid >> 5;
    const int g = l >> 2, cq = l & 3;
    const int wm = wid & 3, wn = wid >> 2;
    const int m0 = (blockIdx.x >> 1) * 128;
    const int f0 = (blockIdx.x & 1) * 128;

    float acc[2][8][4];
    #pragma unroll
    for (int mt = 0; mt < 2; ++mt)
        #pragma unroll
        for (int nt = 0; nt < 8; ++nt)
            #pragma unroll
            for (int q = 0; q < 4; ++q) acc[mt][nt][q] = 0.f;

    // Prologue
    loadB2(sb, f0, 0, 0, tid);
    CP_COMMIT();
    if (tid < 128)
        compute_params2(0, m0 + tid, tid, (float*)(smem + SM2_SW), (int*)(smem + SM2_SO));
    __syncthreads();
    sample2(x, smem, 0, 0, tid);
    CP_WAIT0();
    __syncthreads();

    for (int i = 0; i < 72; ++i) {
        const int s = i & 1;
        if (i < 71) {
            loadB2(sb, f0, i + 1, s ^ 1, tid);
            CP_COMMIT();
            sample2(x, smem, i + 1, s ^ 1, tid);
        }
        // Consume stage s
        {
            const uint32_t* A = (const uint32_t*)(smem + SM2_A + s * 16384);
            const uint32_t* B = (const uint32_t*)(smem + SM2_B + s * 16384);
            const int mA = wm * 32 + g;
            const int xk1 = (mA & 7) * 4;          // (m, m+8, m+16, m+24 share &7? no)
            #pragma unroll
            for (int ks = 0; ks < 4; ++ks) {
                uint32_t a[2][4];
                #pragma unroll
                for (int mt = 0; mt < 2; ++mt) {
                    const int m1 = mA + mt * 16;
                    const int xk = (m1 & 7) * 4;   // == xk1 (mt*16 keeps low 3 bits)
                    const int k1 = (ks * 8 + cq) ^ xk;
                    const int k2 = (ks * 8 + cq + 4) ^ xk;
                    a[mt][0] = A[m1 * 32 + k1];
                    a[mt][1] = A[(m1 + 8) * 32 + k1];
                    a[mt][2] = A[m1 * 32 + k2];
                    a[mt][3] = A[(m1 + 8) * 32 + k2];
                }
                #pragma unroll
                for (int nt = 0; nt < 8; ++nt) {
                    const int nb = ((wn * 8 + nt) * 8 + ks * 2) * 32;
                    uint32_t b[2];
                    b[0] = B[nb + (g ^ (ks * 2)) * 4 + cq];
                    b[1] = B[nb + 32 + (g ^ (ks * 2 + 1)) * 4 + cq];
                    mma_tf32(acc[0][nt], a[0], b);
                    mma_tf32(acc[1][nt], a[1], b);
                }
            }
        }
        const int j2 = i + 2;
        if (j2 <= 71 && (j2 & 7) == 0 && tid < 128) {
            const int kp = j2 >> 3, pb = kp & 1;
            compute_params2(kp, m0 + tid, tid,
                            (float*)(smem + SM2_SW) + pb * 512,
                            (int*)(smem + SM2_SO) + pb * 512);
        }
        if (i < 71) CP_WAIT0();
        __syncthreads();
    }

    // Epilogue: bias + store. c-frag: (g, 2cq), (g, 2cq+1), (g+8, ...), per tile.
    #pragma unroll
    for (int nt = 0; nt < 8; ++nt) {
        const int fl = f0 + wn * 64 + nt * 8 + 2 * cq;
        const float2 bv = *(const float2*)(bias + fl);
        #pragma unroll
        for (int mt = 0; mt < 2; ++mt) {
            const int r0 = m0 + wm * 32 + mt * 16 + g;
            float2 v0, v1;
            v0.x = acc[mt][nt][0] + bv.x;
            v0.y = acc[mt][nt][1] + bv.y;
            v1.x = acc[mt][nt][2] + bv.x;
            v1.y = acc[mt][nt][3] + bv.y;
            *(float2*)(out + (size_t)r0 * 256 + fl) = v0;
            *(float2*)(out + (size_t)(r0 + 8) * 256 + fl) = v1;
        }
    }
}

// ============================ Launch ============================
extern "C" void kernel_launch(void* const* d_in, const int* in_sizes, int n_in,
                              void* d_out, int out_size) {
    (void)in_sizes; (void)n_in; (void)out_size;
    const float* x    = (const float*)d_in[0];
    const float* omw  = (const float*)d_in[1];
    const float* omb  = (const float*)d_in[2];
    const float* W    = (const float*)d_in[3];
    const float* bias = (const float*)d_in[4];
    float* out = (float*)d_out;

    static bool attr_set = false;
    if (!attr_set) {
        cudaFuncSetAttribute(dcn_mma_kernel,
                             cudaFuncAttributeMaxDynamicSharedMemorySize, SM2_TOTAL);
        attr_set = true;
    }

    transpose_w<<<dim3(KTOT / 32, FF / 32), 256>>>(W);
    om_conv_kernel<<<1024, 256>>>(x, omw, omb);
    dcn_mma_kernel<<<512, 256, SM2_TOTAL>>>(x, bias, out);
}

// round 4
// speedup vs baseline: 1.5697x; 1.0569x over previous
#include <cuda_runtime.h>
#include <cstdint>
#include <math.h>

// Problem constants (fixed by the dataset)
#define BB 8
#define HH 64
#define WW 64
#define CC 256
#define FF 256
#define NPIX (BB*HH*WW)   // 32768
#define KTOT 2304         // 9*256

__device__ float g_om[NPIX * 27];
__device__ uint32_t g_Wt[FF * KTOT];   // [256][2304]  Wt[f][k] = tf32(W[k][f])

// ============================ helpers ============================
__device__ __forceinline__ uint32_t smem_u32(const void* p) {
    uint32_t a;
    asm("{ .reg .u64 t; cvta.to.shared.u64 t, %1; cvt.u32.u64 %0, t; }"
        : "=r"(a) : "l"(p));
    return a;
}
__device__ __forceinline__ uint32_t f2tf32(float f) {
    uint32_t o;
    asm("cvt.rna.tf32.f32 %0, %1;" : "=r"(o) : "f"(f));
    return o;
}
#define CP_ASYNC16(dst, src) \
    asm volatile("cp.async.cg.shared.global [%0], [%1], 16;" :: "r"(dst), "l"(src) : "memory")
#define CP_COMMIT() asm volatile("cp.async.commit_group;" ::: "memory")
#define CP_WAIT0()  asm volatile("cp.async.wait_group 0;" ::: "memory")

#define LDSM4(r, a) \
    asm volatile("ldmatrix.sync.aligned.m8n8.x4.shared.b16 {%0,%1,%2,%3}, [%4];" \
        : "=r"((r)[0]), "=r"((r)[1]), "=r"((r)[2]), "=r"((r)[3]) : "r"(a))
#define LDSM2(r, a) \
    asm volatile("ldmatrix.sync.aligned.m8n8.x2.shared.b16 {%0,%1}, [%2];" \
        : "=r"((r)[0]), "=r"((r)[1]) : "r"(a))

__device__ __forceinline__ void mma_tf32(float* c, const uint32_t* a, const uint32_t* b) {
    asm volatile("mma.sync.aligned.m16n8k8.row.col.f32.tf32.tf32.f32 "
        "{%0,%1,%2,%3}, {%4,%5,%6,%7}, {%8,%9}, {%0,%1,%2,%3};"
        : "+f"(c[0]), "+f"(c[1]), "+f"(c[2]), "+f"(c[3])
        : "r"(a[0]), "r"(a[1]), "r"(a[2]), "r"(a[3]), "r"(b[0]), "r"(b[1]));
}

// ============================ Kernel 0: W transpose + tf32 round ==============
__global__ __launch_bounds__(256) void transpose_w(const float* __restrict__ W) {
    __shared__ float t[32][33];
    int k0 = blockIdx.x * 32, f0 = blockIdx.y * 32;
    int tx = threadIdx.x & 31, ty = threadIdx.x >> 5;
    #pragma unroll
    for (int r = 0; r < 32; r += 8)
        t[ty + r][tx] = W[(k0 + ty + r) * 256 + f0 + tx];
    __syncthreads();
    #pragma unroll
    for (int r = 0; r < 32; r += 8)
        g_Wt[(f0 + ty + r) * KTOT + k0 + tx] = f2tf32(t[tx][ty + r]);
}

// ============================ Kernel 1: offset/mask conv (fp32) ==============
__global__ __launch_bounds__(256) void om_conv_kernel(
    const float* __restrict__ x, const float* __restrict__ omw,
    const float* __restrict__ omb)
{
    __shared__ float ws[256 * 32];
    const int bid = blockIdx.x;
    const int xh = bid & 1;
    const int y = (bid >> 1) & 63;
    const int b = bid >> 7;
    const int x0 = xh * 32;
    const int tid = threadIdx.x;
    const int p = tid >> 3;
    const int fg = tid & 7;

    for (int i = tid; i < 256 * 32; i += 256) ws[i] = 0.f;

    float4 acc = make_float4(0.f, 0.f, 0.f, 0.f);
    const int gx = x0 + p;

    for (int tap = 0; tap < 9; ++tap) {
        __syncthreads();
        for (int i = tid; i < 256 * 27; i += 256) {
            int c = i / 27;
            int f = i - c * 27;
            ws[c * 32 + f] = omw[(tap * 256 + c) * 27 + f];
        }
        __syncthreads();
        const int dy = tap / 3;
        const int dx = tap - dy * 3;
        const int sy = y - 1 + dy;
        const int sx = gx - 1 + dx;
        if ((unsigned)sy < 64u && (unsigned)sx < 64u) {
            const float* xr = x + (((b * 64 + sy) * 64) + sx) * 256;
            #pragma unroll 4
            for (int c4 = 0; c4 < 64; ++c4) {
                float4 xv = *(const float4*)(xr + c4 * 4);
                const float* wp = &ws[(c4 * 4) * 32 + fg * 4];
                float4 w0 = *(const float4*)(wp);
                float4 w1 = *(const float4*)(wp + 32);
                float4 w2 = *(const float4*)(wp + 64);
                float4 w3 = *(const float4*)(wp + 96);
                acc.x = fmaf(xv.x, w0.x, acc.x); acc.y = fmaf(xv.x, w0.y, acc.y);
                acc.z = fmaf(xv.x, w0.z, acc.z); acc.w = fmaf(xv.x, w0.w, acc.w);
                acc.x = fmaf(xv.y, w1.x, acc.x); acc.y = fmaf(xv.y, w1.y, acc.y);
                acc.z = fmaf(xv.y, w1.z, acc.z); acc.w = fmaf(xv.y, w1.w, acc.w);
                acc.x = fmaf(xv.z, w2.x, acc.x); acc.y = fmaf(xv.z, w2.y, acc.y);
                acc.z = fmaf(xv.z, w2.z, acc.z); acc.w = fmaf(xv.z, w2.w, acc.w);
                acc.x = fmaf(xv.w, w3.x, acc.x); acc.y = fmaf(xv.w, w3.y, acc.y);
                acc.z = fmaf(xv.w, w3.z, acc.z); acc.w = fmaf(xv.w, w3.w, acc.w);
            }
        }
    }
    const int pix = (b * 64 + y) * 64 + gx;
    float vals[4] = {acc.x, acc.y, acc.z, acc.w};
    #pragma unroll
    for (int ff = 0; ff < 4; ++ff) {
        int f = fg * 4 + ff;
        if (f < 27) {
            float v = vals[ff] + omb[f];
            if (f >= 18) v = 2.f / (1.f + expf(-v));
            g_om[pix * 27 + f] = v;
        }
    }
}

// ============================ Kernel 2: fused sampling + mma TF32 GEMM ========
// CTA: 128 threads (4 warps), tile M=128 x N=128. Grid 512 (256 m x 2 n).
// Warp tile 64x64 (warps 2m x 2n): acc[4 mt][8 nt][4].
// K loop: 72 chunks of 32 (9 kernel points x 8 channel segments).
// A/B smem rows = 128B, 16B-granule XOR swizzle (g ^ (row&7)); ldmatrix reads.
#define SM3_SW 0            // [2][128] float4 bilinear weights (4KB)
#define SM3_SO 4096         // [2][128] int4 corner offsets (4KB)
#define SM3_A  8192         // [2][128][32] tf32 (32KB)
#define SM3_B  40960        // [2][128][32] tf32 (32KB)
#define SM3_TOTAL 73728

__device__ __forceinline__ void compute_params3(int kp, int m, float4* sw4, int4* so4) {
    const float* omp = g_om + m * 27;
    const int y = (m >> 6) & 63, xc = m & 63, b = m >> 12;
    const int ky = kp / 3, kx = kp - ky * 3;
    float py = (float)(y - 1 + ky) + omp[2 * kp];
    float px = (float)(xc - 1 + kx) + omp[2 * kp + 1];
    float msk = omp[18 + kp];
    float y0f = floorf(py), x0f = floorf(px);
    float wy1 = py - y0f, wy0 = 1.f - wy1;
    float wx1 = px - x0f, wx0 = 1.f - wx1;
    int iy0 = (int)y0f, ix0 = (int)x0f;
    int iy1 = iy0 + 1, ix1 = ix0 + 1;
    bool vy0 = (unsigned)iy0 < 64u, vy1 = (unsigned)iy1 < 64u;
    bool vx0 = (unsigned)ix0 < 64u, vx1 = (unsigned)ix1 < 64u;
    int cy0 = min(max(iy0, 0), 63), cy1 = min(max(iy1, 0), 63);
    int cx0 = min(max(ix0, 0), 63), cx1 = min(max(ix1, 0), 63);
    int base = b << 12;
    int4 o;
    o.x = (base + cy0 * 64 + cx0) << 8;
    o.y = (base + cy0 * 64 + cx1) << 8;
    o.z = (base + cy1 * 64 + cx0) << 8;
    o.w = (base + cy1 * 64 + cx1) << 8;
    float4 w;
    w.x = (vy0 && vx0) ? wy0 * wx0 * msk : 0.f;
    w.y = (vy0 && vx1) ? wy0 * wx1 * msk : 0.f;
    w.z = (vy1 && vx0) ? wy1 * wx0 * msk : 0.f;
    w.w = (vy1 && vx1) ? wy1 * wx1 * msk : 0.f;
    *so4 = o;
    *sw4 = w;
}

// Sample chunk j into A stage. 8 lanes per pixel-quad slot; lane owns 4 channels,
// loads all 4 corners itself -> every LDG.128 is 4 dense 128B lines.
__device__ __forceinline__ void sample3(const float* __restrict__ x,
                                        char* smem, int j, int stage, int tid) {
    const int pb = (j >> 3) & 1;
    const float4* SW = (const float4*)(smem + SM3_SW) + pb * 128;
    const int4*   SO = (const int4*)(smem + SM3_SO) + pb * 128;
    uint32_t* A = (uint32_t*)(smem + SM3_A + stage * 16384);
    const int lane = tid & 31, wid = tid >> 5;
    const int l = lane & 7, pq = lane >> 3;
    const int cbase = (j & 7) * 32 + l * 4;
    #pragma unroll
    for (int it = 0; it < 8; ++it) {
        const int px = wid * 32 + it * 4 + pq;
        const float4 w = SW[px];
        const int4 o = SO[px];
        float4 v00 = *(const float4*)(x + o.x + cbase);
        float4 v01 = *(const float4*)(x + o.y + cbase);
        float4 v10 = *(const float4*)(x + o.z + cbase);
        float4 v11 = *(const float4*)(x + o.w + cbase);
        uint4 r;
        r.x = f2tf32(w.x * v00.x + w.y * v01.x + w.z * v10.x + w.w * v11.x);
        r.y = f2tf32(w.x * v00.y + w.y * v01.y + w.z * v10.y + w.w * v11.y);
        r.z = f2tf32(w.x * v00.z + w.y * v01.z + w.z * v10.z + w.w * v11.z);
        r.w = f2tf32(w.x * v00.w + w.y * v01.w + w.z * v10.w + w.w * v11.w);
        const int gran = l ^ (px & 7);
        *(uint4*)(A + px * 32 + gran * 4) = r;
    }
}

// Stage B chunk j: n-major rows (128 rows x 128B), same XOR swizzle.
__device__ __forceinline__ void loadB3(uint32_t sb, int f0, int j, int stage, int tid) {
    const int f = tid;
    const uint32_t dbase = sb + SM3_B + stage * 16384 + f * 128;
    const uint32_t* src = g_Wt + (size_t)(f0 + f) * KTOT + j * 32;
    #pragma unroll
    for (int g = 0; g < 8; ++g)
        CP_ASYNC16(dbase + ((g ^ (f & 7)) * 16), src + g * 4);
}

__global__ __launch_bounds__(128, 2) void dcn_mma_kernel(
    const float* __restrict__ x,      // [8,64,64,256]
    const float* __restrict__ bias,   // [256]
    float* __restrict__ out)          // [32768,256]
{
    extern __shared__ char smem[];
    const uint32_t sb = smem_u32(smem);
    const int tid = threadIdx.x;
    const int lane = tid & 31, wid = tid >> 5;
    const int g = lane >> 2, cq = lane & 3;
    const int wm = wid & 1, wn = wid >> 1;
    const int m0 = (blockIdx.x >> 1) * 128;
    const int f0 = (blockIdx.x & 1) * 128;

    float acc[4][8][4];
    #pragma unroll
    for (int mt = 0; mt < 4; ++mt)
        #pragma unroll
        for (int nt = 0; nt < 8; ++nt)
            #pragma unroll
            for (int q = 0; q < 4; ++q) acc[mt][nt][q] = 0.f;

    float4* SW0 = (float4*)(smem + SM3_SW);
    int4*   SO0 = (int4*)(smem + SM3_SO);

    // ldmatrix address precompute
    const int rowA = wm * 64 + (lane & 15);
    const int hiA = (lane >> 4) & 1;
    uint32_t koffA[4], koffB[4];
    #pragma unroll
    for (int ks = 0; ks < 4; ++ks) {
        koffA[ks] = (uint32_t)((ks * 32 + hiA * 16) ^ ((rowA & 7) * 16));
        koffB[ks] = (uint32_t)((ks * 32 + ((lane >> 3) & 1) * 16) ^ ((lane & 7) * 16));
    }
    const uint32_t rowAoff = (uint32_t)(rowA * 128);
    const uint32_t rowBoff = (uint32_t)((wn * 64 + (lane & 7)) * 128);

    // Prologue
    loadB3(sb, f0, 0, 0, tid);
    CP_COMMIT();
    compute_params3(0, m0 + tid, SW0 + tid, SO0 + tid);
    __syncthreads();
    sample3(x, smem, 0, 0, tid);
    CP_WAIT0();
    __syncthreads();

    for (int i = 0; i < 72; ++i) {
        const int s = i & 1;
        if (i < 71) {
            loadB3(sb, f0, i + 1, s ^ 1, tid);
            CP_COMMIT();
            sample3(x, smem, i + 1, s ^ 1, tid);
        }
        // Consume stage s
        {
            const uint32_t Ab = sb + SM3_A + s * 16384 + rowAoff;
            const uint32_t Bb = sb + SM3_B + s * 16384 + rowBoff;
            #pragma unroll
            for (int ks = 0; ks < 4; ++ks) {
                uint32_t a[4][4];
                #pragma unroll
                for (int mt = 0; mt < 4; ++mt)
                    LDSM4(a[mt], Ab + mt * 2048 + koffA[ks]);
                #pragma unroll
                for (int nt = 0; nt < 8; ++nt) {
                    uint32_t b[2];
                    LDSM2(b, Bb + nt * 1024 + koffB[ks]);
                    #pragma unroll
                    for (int mt = 0; mt < 4; ++mt)
                        mma_tf32(acc[mt][nt], a[mt], b);
                }
            }
        }
        const int j2 = i + 2;
        if (j2 <= 71 && (j2 & 7) == 0) {
            const int kp = j2 >> 3, pb = kp & 1;
            compute_params3(kp, m0 + tid, SW0 + pb * 128 + tid, SO0 + pb * 128 + tid);
        }
        if (i < 71) CP_WAIT0();
        __syncthreads();
    }

    // Epilogue
    #pragma unroll
    for (int nt = 0; nt < 8; ++nt) {
        const int fl = f0 + wn * 64 + nt * 8 + 2 * cq;
        const float2 bv = *(const float2*)(bias + fl);
        #pragma unroll
        for (int mt = 0; mt < 4; ++mt) {
            const int r0 = m0 + wm * 64 + mt * 16 + g;
            float2 v0, v1;
            v0.x = acc[mt][nt][0] + bv.x;
            v0.y = acc[mt][nt][1] + bv.y;
            v1.x = acc[mt][nt][2] + bv.x;
            v1.y = acc[mt][nt][3] + bv.y;
            *(float2*)(out + (size_t)r0 * 256 + fl) = v0;
            *(float2*)(out + (size_t)(r0 + 8) * 256 + fl) = v1;
        }
    }
}

// ============================ Launch ============================
extern "C" void kernel_launch(void* const* d_in, const int* in_sizes, int n_in,
                              void* d_out, int out_size) {
    (void)in_sizes; (void)n_in; (void)out_size;
    const float* x    = (const float*)d_in[0];
    const float* omw  = (const float*)d_in[1];
    const float* omb  = (const float*)d_in[2];
    const float* W    = (const float*)d_in[3];
    const float* bias = (const float*)d_in[4];
    float* out = (float*)d_out;

    static bool attr_set = false;
    if (!attr_set) {
        cudaFuncSetAttribute(dcn_mma_kernel,
                             cudaFuncAttributeMaxDynamicSharedMemorySize, SM3_TOTAL);
        attr_set = true;
    }

    transpose_w<<<dim3(KTOT / 32, FF / 32), 256>>>(W);
    om_conv_kernel<<<1024, 256>>>(x, omw, omb);
    dcn_mma_kernel<<<512, 128, SM3_TOTAL>>>(x, bias, out);
}